// round 8
// baseline (speedup 1.0000x reference)
#include <cuda_runtime.h>
#include <cuda_fp16.h>
#include <cstdint>
#include <math.h>

#define M_DIM 16384
#define K_DIM 768
#define N_DIM 3072

// ---------------- scratch (no cudaMalloc allowed) ----------------
__device__ uint16_t g_A[M_DIM * K_DIM];    // fp16 bits, LN output
__device__ uint16_t g_B[N_DIM * K_DIM];    // fp16 bits, W transposed [N, K]

// ---------------- helpers ----------------
__device__ __forceinline__ uint32_t smem_u32(const void* p) {
    uint32_t a;
    asm("{ .reg .u64 t; cvta.to.shared.u64 t, %1; cvt.u32.u64 %0, t; }" : "=r"(a) : "l"(p));
    return a;
}
__device__ __forceinline__ uint16_t f2h(float x) {
    uint16_t h;
    asm("cvt.rn.f16.f32 %0, %1;" : "=h"(h) : "f"(x));
    return h;
}
__device__ __forceinline__ uint32_t pack_h2(float lo, float hi) {
    uint32_t r;
    asm("cvt.rn.f16x2.f32 %0, %1, %2;" : "=r"(r) : "f"(hi), "f"(lo));
    return r;
}
__device__ __forceinline__ void cp_async16(uint32_t dst, const void* src) {
    asm volatile("cp.async.cg.shared.global [%0], [%1], 16;"
                 :: "r"(dst), "l"(__cvta_generic_to_global(src)) : "memory");
}
#define CP_COMMIT() asm volatile("cp.async.commit_group;" ::: "memory")
#define CP_WAIT(n)  asm volatile("cp.async.wait_group %0;" :: "n"(n) : "memory")

__device__ __forceinline__ void ldmatrix_x4(uint32_t* r, uint32_t addr) {
    asm volatile("ldmatrix.sync.aligned.m8n8.x4.shared.b16 {%0,%1,%2,%3}, [%4];"
                 : "=r"(r[0]), "=r"(r[1]), "=r"(r[2]), "=r"(r[3]) : "r"(addr));
}
__device__ __forceinline__ void mma_f16(float* d, const uint32_t* a,
                                        uint32_t b0, uint32_t b1) {
    asm volatile(
        "mma.sync.aligned.m16n8k16.row.col.f32.f16.f16.f32 "
        "{%0,%1,%2,%3}, {%4,%5,%6,%7}, {%8,%9}, {%0,%1,%2,%3};"
        : "+f"(d[0]), "+f"(d[1]), "+f"(d[2]), "+f"(d[3])
        : "r"(a[0]), "r"(a[1]), "r"(a[2]), "r"(a[3]), "r"(b0), "r"(b1));
}
__device__ __forceinline__ float gelu_exact(float h) {
    return 0.5f * h * (1.0f + erff(h * 0.70710678118654752f));
}

// ---------------------------------------------------------------------------
// Kernel 1: LayerNorm -> fp16 (unchanged from R7)
// ---------------------------------------------------------------------------
__global__ __launch_bounds__(256) void ln_h_kernel(
    const float* __restrict__ x,
    const float* __restrict__ gamma,
    const float* __restrict__ beta)
{
    const int tid = threadIdx.x;
    const int rloc = tid >> 6;
    const int t = tid & 63;
    const int row = blockIdx.x * 4 + rloc;
    const float4* xr = (const float4*)(x + (size_t)row * K_DIM);

    float4 v[3];
    #pragma unroll
    for (int j = 0; j < 3; j++) v[j] = xr[t + 64 * j];

    float s = 0.0f, s2 = 0.0f;
    #pragma unroll
    for (int j = 0; j < 3; j++) {
        s  += v[j].x + v[j].y + v[j].z + v[j].w;
        s2 += v[j].x * v[j].x + v[j].y * v[j].y + v[j].z * v[j].z + v[j].w * v[j].w;
    }
    #pragma unroll
    for (int off = 16; off > 0; off >>= 1) {
        s  += __shfl_xor_sync(0xffffffffu, s,  off);
        s2 += __shfl_xor_sync(0xffffffffu, s2, off);
    }
    __shared__ float red[4][2][2];
    const int wir = (t >> 5);
    if ((t & 31) == 0) { red[rloc][wir][0] = s; red[rloc][wir][1] = s2; }
    __syncthreads();
    s  = red[rloc][0][0] + red[rloc][1][0];
    s2 = red[rloc][0][1] + red[rloc][1][1];

    const float inv_n = 1.0f / (float)K_DIM;
    const float mu  = s * inv_n;
    const float var = fmaxf(s2 * inv_n - mu * mu, 0.0f);
    const float rstd = rsqrtf(var + 1e-12f);

    uint2* outr = (uint2*)(g_A + (size_t)row * K_DIM);
    #pragma unroll
    for (int j = 0; j < 3; j++) {
        const float4 g = ((const float4*)gamma)[t + 64 * j];
        const float4 be = ((const float4*)beta)[t + 64 * j];
        uint2 o;
        o.x = pack_h2((v[j].x - mu) * rstd * g.x + be.x,
                      (v[j].y - mu) * rstd * g.y + be.y);
        o.y = pack_h2((v[j].z - mu) * rstd * g.z + be.z,
                      (v[j].w - mu) * rstd * g.w + be.w);
        outr[t + 64 * j] = o;
    }
}

// ---------------------------------------------------------------------------
// Kernel 2: transpose W [K,N] -> [N,K] fp16 (unchanged from R7)
// ---------------------------------------------------------------------------
__global__ __launch_bounds__(256) void wt_h_kernel(const float* __restrict__ W)
{
    __shared__ float tile[64][33];
    const int tx = threadIdx.x, ty = threadIdx.y;
    const int n0 = blockIdx.x * 32, k0 = blockIdx.y * 64;

    #pragma unroll
    for (int j = 0; j < 8; j++)
        tile[ty + 8 * j][tx] = W[(size_t)(k0 + ty + 8 * j) * N_DIM + n0 + tx];
    __syncthreads();

    uint4 o;
    o.x = pack_h2(tile[ty * 8 + 0][tx], tile[ty * 8 + 1][tx]);
    o.y = pack_h2(tile[ty * 8 + 2][tx], tile[ty * 8 + 3][tx]);
    o.z = pack_h2(tile[ty * 8 + 4][tx], tile[ty * 8 + 5][tx]);
    o.w = pack_h2(tile[ty * 8 + 6][tx], tile[ty * 8 + 7][tx]);
    *(uint4*)&g_B[(size_t)(n0 + tx) * K_DIM + k0 + ty * 8] = o;
}

// ---------------------------------------------------------------------------
// Kernel 3: HYBRID GEMM. Per 12-block group: 11 tensor CTAs (N cols 0..2815)
// + 1 FFMA CTA (N cols 2816..3071). Both: bias + exact erf GELU epilogue.
// ---------------------------------------------------------------------------
#define BM 128
#define BN 128
#define BK 32
#define ROWH 40
#define NSTEP 24
#define NSTAGE 3
#define STAGEA (BM * ROWH * 2)        // 10240 B
#define POOL_BYTES (NSTAGE * STAGEA * 2)  // 61440 B

// FFMA sub-kernel tiles (aliased into pool)
#define BKF 16
#define FROW 132                      // floats per smem row (128 + 4 pad)

__global__ __launch_bounds__(256, 2) void gemm_hybrid_kernel(
    const float* __restrict__ bias, float* __restrict__ C)
{
    __shared__ __align__(16) char s_pool[POOL_BYTES];

    const int tid = threadIdx.x;
    const int bx = blockIdx.x;
    const int grp = bx / 12;
    const int r12 = bx - grp * 12;

    if (r12 < 11) {
        // ================= TENSOR ROLE (unchanged mainloop) =================
        const int id = grp * 11 + r12;           // 0..2815
        const int bn = (id % 22) * BN;           // cols 0..2815
        const int bm = (id / 22) * BM;
        const int wid = tid >> 5, lane = tid & 31;
        const int wm = (wid >> 1) * 32;
        const int wn = (wid & 1) * 64;

        float acc[2][8][4];
        #pragma unroll
        for (int mt = 0; mt < 2; mt++)
            #pragma unroll
            for (int nt = 0; nt < 8; nt++)
                #pragma unroll
                for (int q = 0; q < 4; q++) acc[mt][nt][q] = 0.0f;

        const uint32_t sA0 = smem_u32(s_pool);
        const uint32_t sB0 = sA0 + NSTAGE * STAGEA;

        const int r_ld = tid >> 2;
        const int c_ld = (tid & 3) * 8;

        auto load_stage = [&](int st, int step) {
            const int k0 = step * BK;
            #pragma unroll
            for (int i = 0; i < 2; i++) {
                const int rr = r_ld + i * 64;
                const uint32_t soff = (uint32_t)(rr * ROWH + c_ld) * 2;
                cp_async16(sA0 + st * STAGEA + soff,
                           g_A + (size_t)(bm + rr) * K_DIM + k0 + c_ld);
                cp_async16(sB0 + st * STAGEA + soff,
                           g_B + (size_t)(bn + rr) * K_DIM + k0 + c_ld);
            }
            CP_COMMIT();
        };

        load_stage(0, 0);
        load_stage(1, 1);

        for (int step = 0; step < NSTEP; step++) {
            const int st = step % NSTAGE;
            if (step < NSTEP - 1) { CP_WAIT(1); } else { CP_WAIT(0); }
            __syncthreads();

            #pragma unroll
            for (int kk = 0; kk < 2; kk++) {
                const int chunk = kk * 2 + (lane >> 4);
                uint32_t a[2][4];
                #pragma unroll
                for (int mt = 0; mt < 2; mt++) {
                    const int row = wm + mt * 16 + (lane & 15);
                    ldmatrix_x4(a[mt], sA0 + st * STAGEA
                                       + (uint32_t)(row * ROWH) * 2 + chunk * 16);
                }
                uint32_t b[4][4];
                #pragma unroll
                for (int g = 0; g < 4; g++) {
                    const int row = wn + g * 16 + (lane & 15);
                    ldmatrix_x4(b[g], sB0 + st * STAGEA
                                      + (uint32_t)(row * ROWH) * 2 + chunk * 16);
                }
                #pragma unroll
                for (int mt = 0; mt < 2; mt++)
                    #pragma unroll
                    for (int nt = 0; nt < 8; nt++)
                        mma_f16(acc[mt][nt], a[mt],
                                b[nt >> 1][nt & 1], b[nt >> 1][2 + (nt & 1)]);
            }
            if (step + 2 < NSTEP) load_stage((step + 2) % NSTAGE, step + 2);
        }

        const int r0 = bm + wm + (lane >> 2);
        const int c0 = bn + wn + (lane & 3) * 2;
        #pragma unroll
        for (int mt = 0; mt < 2; mt++) {
            #pragma unroll
            for (int nt = 0; nt < 8; nt++) {
                const int col = c0 + nt * 8;
                const float b0 = __ldg(&bias[col]), b1 = __ldg(&bias[col + 1]);
                #pragma unroll
                for (int half = 0; half < 2; half++) {
                    const int row = r0 + mt * 16 + half * 8;
                    float2 o;
                    o.x = gelu_exact(acc[mt][nt][half * 2 + 0] + b0);
                    o.y = gelu_exact(acc[mt][nt][half * 2 + 1] + b1);
                    *(float2*)&C[(size_t)row * N_DIM + col] = o;
                }
            }
        }
    } else {
        // ================= FFMA ROLE (fp32 SGEMM on fp16 operands) ==========
        const int id = grp;                       // 0..255
        const int bn = 2816 + (id & 1) * BN;      // cols 2816..3071
        const int bm = (id >> 1) * BM;

        float* Asf = (float*)s_pool;              // [BKF][FROW]
        float* Bsf = Asf + BKF * FROW;            // [BKF][FROW]

        const int tx = tid & 15;                  // n microtile
        const int ty = tid >> 4;                  // m microtile

        float acc[8][8];
        #pragma unroll
        for (int i = 0; i < 8; i++)
            #pragma unroll
            for (int j = 0; j < 8; j++) acc[i][j] = 0.0f;

        // load geometry: 128 rows x 16 k fp16 per tile; thread -> 1 uint4 (8 halves)
        const int lrow = tid >> 1;
        const int lc8  = (tid & 1) * 8;

        for (int k0 = 0; k0 < K_DIM; k0 += BKF) {
            uint4 av = *(const uint4*)&g_A[(size_t)(bm + lrow) * K_DIM + k0 + lc8];
            uint4 bv = *(const uint4*)&g_B[(size_t)(bn + lrow) * K_DIM + k0 + lc8];
            const uint32_t* au = (const uint32_t*)&av;
            const uint32_t* bu = (const uint32_t*)&bv;
            #pragma unroll
            for (int p = 0; p < 4; p++) {
                float2 af = __half22float2(*(const __half2*)&au[p]);
                float2 bf = __half22float2(*(const __half2*)&bu[p]);
                Asf[(lc8 + 2 * p + 0) * FROW + lrow] = af.x;
                Asf[(lc8 + 2 * p + 1) * FROW + lrow] = af.y;
                Bsf[(lc8 + 2 * p + 0) * FROW + lrow] = bf.x;
                Bsf[(lc8 + 2 * p + 1) * FROW + lrow] = bf.y;
            }
            __syncthreads();

            #pragma unroll
            for (int kk = 0; kk < BKF; kk++) {
                float4 a0 = *(const float4*)&Asf[kk * FROW + ty * 8];
                float4 a1 = *(const float4*)&Asf[kk * FROW + ty * 8 + 4];
                float4 b0 = *(const float4*)&Bsf[kk * FROW + tx * 8];
                float4 b1 = *(const float4*)&Bsf[kk * FROW + tx * 8 + 4];
                float ar[8] = {a0.x, a0.y, a0.z, a0.w, a1.x, a1.y, a1.z, a1.w};
                float br[8] = {b0.x, b0.y, b0.z, b0.w, b1.x, b1.y, b1.z, b1.w};
                #pragma unroll
                for (int i = 0; i < 8; i++)
                    #pragma unroll
                    for (int j = 0; j < 8; j++)
                        acc[i][j] = fmaf(ar[i], br[j], acc[i][j]);
            }
            __syncthreads();
        }

        #pragma unroll
        for (int i = 0; i < 8; i++) {
            const int row = bm + ty * 8 + i;
            float* crow = C + (size_t)row * N_DIM + bn + tx * 8;
            #pragma unroll
            for (int j4 = 0; j4 < 2; j4++) {
                float4 o;
                #pragma unroll
                for (int j = 0; j < 4; j++) {
                    const int col = bn + tx * 8 + j4 * 4 + j;
                    ((float*)&o)[j] = gelu_exact(acc[i][j4 * 4 + j] + __ldg(&bias[col]));
                }
                *(float4*)(crow + j4 * 4) = o;
            }
        }
    }
}

// ---------------------------------------------------------------------------
extern "C" void kernel_launch(void* const* d_in, const int* in_sizes, int n_in,
                              void* d_out, int out_size)
{
    const float* x     = (const float*)d_in[0];
    const float* gamma = (const float*)d_in[1];
    const float* beta  = (const float*)d_in[2];
    const float* W     = (const float*)d_in[3];
    const float* b     = (const float*)d_in[4];
    float* out = (float*)d_out;

    ln_h_kernel<<<M_DIM / 4, 256>>>(x, gamma, beta);
    wt_h_kernel<<<dim3(N_DIM / 32, K_DIM / 64), dim3(32, 8)>>>(W);
    gemm_hybrid_kernel<<<3072, 256>>>(b, out);
}

// round 9
// speedup vs baseline: 1.2319x; 1.2319x over previous
#include <cuda_runtime.h>
#include <cuda_fp16.h>
#include <cstdint>
#include <math.h>

#define M_DIM 16384
#define K_DIM 768
#define N_DIM 3072

// ---------------- scratch (no cudaMalloc allowed) ----------------
__device__ uint16_t g_A[M_DIM * K_DIM];    // fp16 bits, LN output
__device__ uint16_t g_B[N_DIM * K_DIM];    // fp16 bits, W transposed [N, K]

// ---------------- helpers ----------------
__device__ __forceinline__ uint32_t smem_u32(const void* p) {
    uint32_t a;
    asm("{ .reg .u64 t; cvta.to.shared.u64 t, %1; cvt.u32.u64 %0, t; }" : "=r"(a) : "l"(p));
    return a;
}
__device__ __forceinline__ uint32_t pack_h2(float lo, float hi) {
    uint32_t r;
    asm("cvt.rn.f16x2.f32 %0, %1, %2;" : "=r"(r) : "f"(hi), "f"(lo));
    return r;
}
__device__ __forceinline__ void cp_async16(uint32_t dst, const void* src) {
    asm volatile("cp.async.cg.shared.global [%0], [%1], 16;"
                 :: "r"(dst), "l"(__cvta_generic_to_global(src)) : "memory");
}
#define CP_COMMIT() asm volatile("cp.async.commit_group;" ::: "memory")
#define CP_WAIT(n)  asm volatile("cp.async.wait_group %0;" :: "n"(n) : "memory")

__device__ __forceinline__ void ldmatrix_x4(uint32_t* r, uint32_t addr) {
    asm volatile("ldmatrix.sync.aligned.m8n8.x4.shared.b16 {%0,%1,%2,%3}, [%4];"
                 : "=r"(r[0]), "=r"(r[1]), "=r"(r[2]), "=r"(r[3]) : "r"(addr));
}
// f16-accumulator HMMA (2 packed f16x2 regs for D/C)
__device__ __forceinline__ void mma_f16acc(uint32_t* d, const uint32_t* a,
                                           uint32_t b0, uint32_t b1) {
    asm volatile(
        "mma.sync.aligned.m16n8k16.row.col.f16.f16.f16.f16 "
        "{%0,%1}, {%2,%3,%4,%5}, {%6,%7}, {%0,%1};"
        : "+r"(d[0]), "+r"(d[1])
        : "r"(a[0]), "r"(a[1]), "r"(a[2]), "r"(a[3]), "r"(b0), "r"(b1));
}
__device__ __forceinline__ float gelu_exact(float h) {
    return 0.5f * h * (1.0f + erff(h * 0.70710678118654752f));
}

// ---------------------------------------------------------------------------
// Kernel 1: LayerNorm -> fp16 (unchanged)
// ---------------------------------------------------------------------------
__global__ __launch_bounds__(256) void ln_h_kernel(
    const float* __restrict__ x,
    const float* __restrict__ gamma,
    const float* __restrict__ beta)
{
    const int tid = threadIdx.x;
    const int rloc = tid >> 6;
    const int t = tid & 63;
    const int row = blockIdx.x * 4 + rloc;
    const float4* xr = (const float4*)(x + (size_t)row * K_DIM);

    float4 v[3];
    #pragma unroll
    for (int j = 0; j < 3; j++) v[j] = xr[t + 64 * j];

    float s = 0.0f, s2 = 0.0f;
    #pragma unroll
    for (int j = 0; j < 3; j++) {
        s  += v[j].x + v[j].y + v[j].z + v[j].w;
        s2 += v[j].x * v[j].x + v[j].y * v[j].y + v[j].z * v[j].z + v[j].w * v[j].w;
    }
    #pragma unroll
    for (int off = 16; off > 0; off >>= 1) {
        s  += __shfl_xor_sync(0xffffffffu, s,  off);
        s2 += __shfl_xor_sync(0xffffffffu, s2, off);
    }
    __shared__ float red[4][2][2];
    const int wir = (t >> 5);
    if ((t & 31) == 0) { red[rloc][wir][0] = s; red[rloc][wir][1] = s2; }
    __syncthreads();
    s  = red[rloc][0][0] + red[rloc][1][0];
    s2 = red[rloc][0][1] + red[rloc][1][1];

    const float inv_n = 1.0f / (float)K_DIM;
    const float mu  = s * inv_n;
    const float var = fmaxf(s2 * inv_n - mu * mu, 0.0f);
    const float rstd = rsqrtf(var + 1e-12f);

    uint2* outr = (uint2*)(g_A + (size_t)row * K_DIM);
    #pragma unroll
    for (int j = 0; j < 3; j++) {
        const float4 g = ((const float4*)gamma)[t + 64 * j];
        const float4 be = ((const float4*)beta)[t + 64 * j];
        uint2 o;
        o.x = pack_h2((v[j].x - mu) * rstd * g.x + be.x,
                      (v[j].y - mu) * rstd * g.y + be.y);
        o.y = pack_h2((v[j].z - mu) * rstd * g.z + be.z,
                      (v[j].w - mu) * rstd * g.w + be.w);
        outr[t + 64 * j] = o;
    }
}

// ---------------------------------------------------------------------------
// Kernel 2: transpose W [K,N] -> [N,K] fp16 (unchanged)
// ---------------------------------------------------------------------------
__global__ __launch_bounds__(256) void wt_h_kernel(const float* __restrict__ W)
{
    __shared__ float tile[64][33];
    const int tx = threadIdx.x, ty = threadIdx.y;
    const int n0 = blockIdx.x * 32, k0 = blockIdx.y * 64;

    #pragma unroll
    for (int j = 0; j < 8; j++)
        tile[ty + 8 * j][tx] = W[(size_t)(k0 + ty + 8 * j) * N_DIM + n0 + tx];
    __syncthreads();

    uint4 o;
    o.x = pack_h2(tile[ty * 8 + 0][tx], tile[ty * 8 + 1][tx]);
    o.y = pack_h2(tile[ty * 8 + 2][tx], tile[ty * 8 + 3][tx]);
    o.z = pack_h2(tile[ty * 8 + 4][tx], tile[ty * 8 + 5][tx]);
    o.w = pack_h2(tile[ty * 8 + 6][tx], tile[ty * 8 + 7][tx]);
    *(uint4*)&g_B[(size_t)(n0 + tx) * K_DIM + k0 + ty * 8] = o;
}

// ---------------------------------------------------------------------------
// Kernel 3: fp16 GEMM with f16-accumulator HMMA, windowed fp32 promotion.
// CTA 128x128, BK=32, 3-stage cp.async, window = 2 steps (K=64).
// ---------------------------------------------------------------------------
#define BM 128
#define BN 128
#define BK 32
#define ROWH 40
#define NSTEP 24
#define NSTAGE 3

__global__ __launch_bounds__(256, 1) void gemm_f16w_kernel(
    const float* __restrict__ bias, float* __restrict__ C)
{
    __shared__ uint16_t As[NSTAGE][BM * ROWH];
    __shared__ uint16_t Bs[NSTAGE][BN * ROWH];

    const int tid = threadIdx.x;
    const int wid = tid >> 5, lane = tid & 31;
    const int bn = blockIdx.x * BN;
    const int bm = blockIdx.y * BM;
    const int wm = (wid >> 1) * 32;   // 4 warps along M
    const int wn = (wid & 1) * 64;    // 2 warps along N

    float acc[2][8][4];               // persistent fp32 accumulators
    #pragma unroll
    for (int mt = 0; mt < 2; mt++)
        #pragma unroll
        for (int nt = 0; nt < 8; nt++)
            #pragma unroll
            for (int q = 0; q < 4; q++) acc[mt][nt][q] = 0.0f;

    uint32_t dh[2][8][2];             // f16 window accumulators (f16x2 pairs)

    const uint32_t sA0 = smem_u32(&As[0][0]);
    const uint32_t sB0 = smem_u32(&Bs[0][0]);
    const uint32_t stageA = (uint32_t)(BM * ROWH * 2);
    const uint32_t stageB = (uint32_t)(BN * ROWH * 2);

    const int r_ld  = tid >> 2;
    const int c_ld  = (tid & 3) * 8;

    auto load_stage = [&](int st, int step) {
        const int k0 = step * BK;
        #pragma unroll
        for (int i = 0; i < 2; i++) {
            const int r = r_ld + i * 64;
            const uint32_t soff = (uint32_t)(r * ROWH + c_ld) * 2;
            cp_async16(sA0 + st * stageA + soff,
                       g_A + (size_t)(bm + r) * K_DIM + k0 + c_ld);
            cp_async16(sB0 + st * stageB + soff,
                       g_B + (size_t)(bn + r) * K_DIM + k0 + c_ld);
        }
        CP_COMMIT();
    };

    load_stage(0, 0);
    load_stage(1, 1);

    for (int step = 0; step < NSTEP; step++) {
        const int st = step % NSTAGE;
        if (step < NSTEP - 1) { CP_WAIT(1); } else { CP_WAIT(0); }
        __syncthreads();

        if ((step & 1) == 0) {
            // window start: zero f16 accumulators
            #pragma unroll
            for (int mt = 0; mt < 2; mt++)
                #pragma unroll
                for (int nt = 0; nt < 8; nt++) {
                    dh[mt][nt][0] = 0u;
                    dh[mt][nt][1] = 0u;
                }
        }

        #pragma unroll
        for (int kk = 0; kk < 2; kk++) {        // two k16 steps per BK=32
            const int chunk = kk * 2 + (lane >> 4);
            uint32_t a[2][4];
            #pragma unroll
            for (int mt = 0; mt < 2; mt++) {
                const int row = wm + mt * 16 + (lane & 15);
                ldmatrix_x4(a[mt], sA0 + st * stageA
                                   + (uint32_t)(row * ROWH) * 2 + chunk * 16);
            }
            uint32_t b[4][4];
            #pragma unroll
            for (int g = 0; g < 4; g++) {
                const int row = wn + g * 16 + (lane & 15);
                ldmatrix_x4(b[g], sB0 + st * stageB
                                  + (uint32_t)(row * ROWH) * 2 + chunk * 16);
            }
            #pragma unroll
            for (int mt = 0; mt < 2; mt++)
                #pragma unroll
                for (int nt = 0; nt < 8; nt++)
                    mma_f16acc(dh[mt][nt], a[mt],
                               b[nt >> 1][nt & 1], b[nt >> 1][2 + (nt & 1)]);
        }

        if ((step & 1) == 1) {
            // window end: promote f16 partials into fp32 accumulators
            #pragma unroll
            for (int mt = 0; mt < 2; mt++)
                #pragma unroll
                for (int nt = 0; nt < 8; nt++) {
                    float2 p0 = __half22float2(*(const __half2*)&dh[mt][nt][0]);
                    float2 p1 = __half22float2(*(const __half2*)&dh[mt][nt][1]);
                    acc[mt][nt][0] += p0.x;
                    acc[mt][nt][1] += p0.y;
                    acc[mt][nt][2] += p1.x;
                    acc[mt][nt][3] += p1.y;
                }
        }

        if (step + 2 < NSTEP) load_stage((step + 2) % NSTAGE, step + 2);
    }

    // epilogue: bias + exact erf GELU
    const int r0 = bm + wm + (lane >> 2);
    const int c0 = bn + wn + (lane & 3) * 2;
    #pragma unroll
    for (int mt = 0; mt < 2; mt++) {
        #pragma unroll
        for (int nt = 0; nt < 8; nt++) {
            const int col = c0 + nt * 8;
            const float b0 = __ldg(&bias[col]), b1 = __ldg(&bias[col + 1]);
            #pragma unroll
            for (int half = 0; half < 2; half++) {
                const int row = r0 + mt * 16 + half * 8;
                float2 o;
                o.x = gelu_exact(acc[mt][nt][half * 2 + 0] + b0);
                o.y = gelu_exact(acc[mt][nt][half * 2 + 1] + b1);
                *(float2*)&C[(size_t)row * N_DIM + col] = o;
            }
        }
    }
}

// ---------------------------------------------------------------------------
extern "C" void kernel_launch(void* const* d_in, const int* in_sizes, int n_in,
                              void* d_out, int out_size)
{
    const float* x     = (const float*)d_in[0];
    const float* gamma = (const float*)d_in[1];
    const float* beta  = (const float*)d_in[2];
    const float* W     = (const float*)d_in[3];
    const float* b     = (const float*)d_in[4];
    float* out = (float*)d_out;

    ln_h_kernel<<<M_DIM / 4, 256>>>(x, gamma, beta);
    wt_h_kernel<<<dim3(N_DIM / 32, K_DIM / 64), dim3(32, 8)>>>(W);
    gemm_f16w_kernel<<<dim3(N_DIM / BN, M_DIM / BM), 256>>>(b, out);
}